// round 3
// baseline (speedup 1.0000x reference)
#include <cuda_runtime.h>
#include <cuda_bf16.h>

#define NN 100000
#define NE 3200000
#define DIN 128
#define DHID 64
#define DOUT 40

// Scratch (static __device__ arrays — no allocation). 16B-aligned for vector ops.
__device__ __align__(16) float g_h1[NN * DHID];      // x@W1
__device__ __align__(16) float g_h1agg[NN * DHID];   // relu(spmm1)
__device__ __align__(16) float g_h2[NN * DOUT];      // h1agg@W2
__device__ int   g_dst[NE];
__device__ int   g_src[NE];
__device__ int2  g_edges[NE];      // CSR payload: (src, w-bits), sorted by dst
__device__ int   g_deg[NN];        // histogram
__device__ int   g_cur[NN];        // scatter cursors
__device__ int   g_rowptr[NN + 1];
__device__ int   g_is_i32;

// ---------------------------------------------------------------------------
// packed fp32x2 FMA (Blackwell FFMA2 — only reachable via PTX)
// ---------------------------------------------------------------------------
union F2U { float2 f; unsigned long long u; };
__device__ __forceinline__ float2 ffma2(float2 a, float2 b, float2 c) {
    F2U ua, ub, uc, ud;
    ua.f = a; ub.f = b; uc.f = c;
    asm("fma.rn.f32x2 %0, %1, %2, %3;" : "=l"(ud.u) : "l"(ua.u), "l"(ub.u), "l"(uc.u));
    return ud.f;
}

// ---------------------------------------------------------------------------
// dtype detection (int32 vs int64 edge_index), deterministic
// ---------------------------------------------------------------------------
__global__ void detect_dtype(const long long* __restrict__ ei) {
    __shared__ int bad;
    if (threadIdx.x == 0) bad = 0;
    __syncthreads();
    long long v = ei[threadIdx.x];   // first 2KB, safe for either dtype
    if (v < 0 || v >= NN) atomicOr(&bad, 1);
    __syncthreads();
    if (threadIdx.x == 0) g_is_i32 = bad;
}

// ---------------------------------------------------------------------------
// zero degree histogram
// ---------------------------------------------------------------------------
__global__ void zero_deg() {
    int i = blockIdx.x * blockDim.x + threadIdx.x;
    if (i < NN) g_deg[i] = 0;
}

// ---------------------------------------------------------------------------
// convert edges (clamped) + degree histogram
// ---------------------------------------------------------------------------
__global__ void convert_hist(const void* __restrict__ eiv) {
    int i = blockIdx.x * blockDim.x + threadIdx.x;   // grid covers NE exactly
    int d, s;
    if (g_is_i32) {
        const int* e = (const int*)eiv;
        d = e[i]; s = e[NE + i];
    } else {
        const long long* e = (const long long*)eiv;
        d = (int)e[i]; s = (int)e[NE + i];
    }
    d = min(max(d, 0), NN - 1);
    s = min(max(s, 0), NN - 1);
    g_dst[i] = d;
    g_src[i] = s;
    atomicAdd(&g_deg[d], 1);
}

// ---------------------------------------------------------------------------
// exclusive scan of degrees -> rowptr + cursors. Single block, 1024 threads,
// each handles up to 98 contiguous rows (1024*98 = 100352 >= NN).
// ---------------------------------------------------------------------------
__global__ void scan_rows() {
    __shared__ int sums[1024];
    int t = threadIdx.x;
    int beg = t * 98;
    int end = min(beg + 98, NN);
    int s = 0;
    for (int r = beg; r < end; r++) s += g_deg[r];
    sums[t] = s;
    __syncthreads();
    // Hillis-Steele inclusive scan
    for (int off = 1; off < 1024; off <<= 1) {
        int v = (t >= off) ? sums[t - off] : 0;
        __syncthreads();
        sums[t] += v;
        __syncthreads();
    }
    int base = (t == 0) ? 0 : sums[t - 1];
    for (int r = beg; r < end; r++) {
        g_rowptr[r] = base;
        g_cur[r]    = base;
        base += g_deg[r];
    }
    if (t == 1023) g_rowptr[NN] = base;   // == NE
}

// ---------------------------------------------------------------------------
// scatter edges into CSR order (packed (src, w) per edge)
// ---------------------------------------------------------------------------
__global__ void scatter(const float* __restrict__ ew) {
    int e = blockIdx.x * blockDim.x + threadIdx.x;   // grid covers NE exactly
    int d = g_dst[e];
    int pos = atomicAdd(&g_cur[d], 1);
    g_edges[pos] = make_int2(g_src[e], __float_as_int(ew[e]));
}

// ---------------------------------------------------------------------------
// GEMM1: h1 = x[NN,128] @ W1[128,64]
// Block tile 128x64, 256 threads, thread tile 8x4, f32x2 FMAs.
// ---------------------------------------------------------------------------
__global__ void gemm1(const float* __restrict__ x, const float* __restrict__ W1) {
    extern __shared__ float sm[];
    float (*Xs)[130] = (float(*)[130])sm;     // 128 x 130 (pad: conflict-free)
    float* Ws = sm + 128 * 130;               // [k][n] 128x64

    const int tid  = threadIdx.x;
    const int row0 = blockIdx.x * 128;

    // load W1: 2048 float4
    {
        const float4* W4 = (const float4*)W1;
        float4*       Wd = (float4*)Ws;
        #pragma unroll
        for (int i = 0; i < 8; i++) Wd[tid + 256 * i] = W4[tid + 256 * i];
    }
    // load X tile: one warp covers one row per step (coalesced)
    {
        const float4* X4 = (const float4*)x;
        #pragma unroll
        for (int i = 0; i < 16; i++) {
            int idx = tid + 256 * i;
            int r = idx >> 5, c4 = idx & 31;
            int gr = row0 + r;
            if (gr >= NN) gr = NN - 1;  // clamp (only last block)
            float4 v = X4[(size_t)gr * 32 + c4];
            Xs[r][c4 * 4 + 0] = v.x;
            Xs[r][c4 * 4 + 1] = v.y;
            Xs[r][c4 * 4 + 2] = v.z;
            Xs[r][c4 * 4 + 3] = v.w;
        }
    }
    __syncthreads();

    const int ty = tid >> 4;   // 0..15 -> rows ty*8..+7
    const int tx = tid & 15;   // 0..15 -> cols tx*4..+3

    float2 acc[8][2];
    #pragma unroll
    for (int r = 0; r < 8; r++) { acc[r][0] = make_float2(0.f, 0.f); acc[r][1] = make_float2(0.f, 0.f); }

    for (int k = 0; k < DIN; k++) {
        float4 w = *(const float4*)&Ws[k * DHID + tx * 4];
        float2 w01 = make_float2(w.x, w.y);
        float2 w23 = make_float2(w.z, w.w);
        #pragma unroll
        for (int r = 0; r < 8; r++) {
            float xv = Xs[ty * 8 + r][k];
            float2 xx = make_float2(xv, xv);
            acc[r][0] = ffma2(xx, w01, acc[r][0]);
            acc[r][1] = ffma2(xx, w23, acc[r][1]);
        }
    }

    float4* out = (float4*)g_h1;
    #pragma unroll
    for (int r = 0; r < 8; r++) {
        int gr = row0 + ty * 8 + r;
        if (gr < NN) {
            float4 v = make_float4(acc[r][0].x, acc[r][0].y, acc[r][1].x, acc[r][1].y);
            out[(size_t)gr * 16 + tx] = v;
        }
    }
}

// ---------------------------------------------------------------------------
// SpMM1 (CSR pull) + ReLU: h1agg[row] = relu(sum_e w_e * h1[src_e])
// One warp per row; lane holds cols {lane, lane+32}.
// ---------------------------------------------------------------------------
__global__ void spmm1_csr() {
    int row  = blockIdx.x * 8 + (threadIdx.x >> 5);
    int lane = threadIdx.x & 31;
    int beg = g_rowptr[row];
    int end = g_rowptr[row + 1];

    float a0 = 0.f, a1 = 0.f;
    int i = beg;
    for (; i + 4 <= end; i += 4) {
        int2 e0 = g_edges[i + 0];
        int2 e1 = g_edges[i + 1];
        int2 e2 = g_edges[i + 2];
        int2 e3 = g_edges[i + 3];
        const float* p0 = g_h1 + (size_t)e0.x * DHID;
        const float* p1 = g_h1 + (size_t)e1.x * DHID;
        const float* p2 = g_h1 + (size_t)e2.x * DHID;
        const float* p3 = g_h1 + (size_t)e3.x * DHID;
        float w0 = __int_as_float(e0.y), w1 = __int_as_float(e1.y);
        float w2 = __int_as_float(e2.y), w3 = __int_as_float(e3.y);
        float v00 = p0[lane], v01 = p0[32 + lane];
        float v10 = p1[lane], v11 = p1[32 + lane];
        float v20 = p2[lane], v21 = p2[32 + lane];
        float v30 = p3[lane], v31 = p3[32 + lane];
        a0 += w0 * v00; a1 += w0 * v01;
        a0 += w1 * v10; a1 += w1 * v11;
        a0 += w2 * v20; a1 += w2 * v21;
        a0 += w3 * v30; a1 += w3 * v31;
    }
    for (; i < end; i++) {
        int2 e = g_edges[i];
        const float* p = g_h1 + (size_t)e.x * DHID;
        float w = __int_as_float(e.y);
        a0 += w * p[lane];
        a1 += w * p[32 + lane];
    }
    g_h1agg[(size_t)row * DHID + lane]      = fmaxf(a0, 0.f);
    g_h1agg[(size_t)row * DHID + 32 + lane] = fmaxf(a1, 0.f);
}

// ---------------------------------------------------------------------------
// GEMM2: h2 = h1agg[NN,64] @ W2[64,40]   (input already ReLU'd)
// ---------------------------------------------------------------------------
__global__ void gemm2(const float* __restrict__ W2) {
    __shared__ float Hs[64][DHID + 1];
    __shared__ float Ws[DHID * DOUT];

    const int tid  = threadIdx.x;
    const int row0 = blockIdx.x * 64;

    #pragma unroll
    for (int i = 0; i < 16; i++) {
        int idx = tid + 256 * i;
        int r = idx >> 6, c = idx & 63;
        float v = 0.f;
        if (row0 + r < NN) v = g_h1agg[(size_t)(row0 + r) * DHID + c];
        Hs[r][c] = v;
    }
    #pragma unroll
    for (int i = 0; i < 10; i++) Ws[tid + 256 * i] = W2[tid + 256 * i];
    __syncthreads();

    const int ty = tid >> 3;  // 0..31 -> rows ty*2, ty*2+1
    const int tx = tid & 7;   // 0..7  -> cols tx*5..tx*5+4

    float acc[2][5] = {};
    #pragma unroll 8
    for (int k = 0; k < DHID; k++) {
        float h0  = Hs[ty * 2 + 0][k];
        float h1v = Hs[ty * 2 + 1][k];
        #pragma unroll
        for (int j = 0; j < 5; j++) {
            float w = Ws[k * DOUT + tx * 5 + j];
            acc[0][j] += h0 * w;
            acc[1][j] += h1v * w;
        }
    }

    #pragma unroll
    for (int i = 0; i < 2; i++) {
        int r = row0 + ty * 2 + i;
        if (r < NN) {
            #pragma unroll
            for (int j = 0; j < 5; j++)
                g_h2[(size_t)r * DOUT + tx * 5 + j] = acc[i][j];
        }
    }
}

// ---------------------------------------------------------------------------
// SpMM2 (CSR pull) + log_softmax fused. One warp per row.
// Lane holds col lane; lanes 0..7 also hold col 32+lane.
// ---------------------------------------------------------------------------
__global__ void spmm2_lsm(float* __restrict__ out) {
    int row  = blockIdx.x * 8 + (threadIdx.x >> 5);
    int lane = threadIdx.x & 31;
    bool hi  = lane < 8;
    int beg = g_rowptr[row];
    int end = g_rowptr[row + 1];

    float a0 = 0.f, a1 = 0.f;
    int i = beg;
    for (; i + 4 <= end; i += 4) {
        int2 e0 = g_edges[i + 0];
        int2 e1 = g_edges[i + 1];
        int2 e2 = g_edges[i + 2];
        int2 e3 = g_edges[i + 3];
        const float* p0 = g_h2 + (size_t)e0.x * DOUT;
        const float* p1 = g_h2 + (size_t)e1.x * DOUT;
        const float* p2 = g_h2 + (size_t)e2.x * DOUT;
        const float* p3 = g_h2 + (size_t)e3.x * DOUT;
        float w0 = __int_as_float(e0.y), w1 = __int_as_float(e1.y);
        float w2 = __int_as_float(e2.y), w3 = __int_as_float(e3.y);
        a0 += w0 * p0[lane];
        a0 += w1 * p1[lane];
        a0 += w2 * p2[lane];
        a0 += w3 * p3[lane];
        if (hi) {
            a1 += w0 * p0[32 + lane];
            a1 += w1 * p1[32 + lane];
            a1 += w2 * p2[32 + lane];
            a1 += w3 * p3[32 + lane];
        }
    }
    for (; i < end; i++) {
        int2 e = g_edges[i];
        const float* p = g_h2 + (size_t)e.x * DOUT;
        float w = __int_as_float(e.y);
        a0 += w * p[lane];
        if (hi) a1 += w * p[32 + lane];
    }

    // log_softmax over the 40 values held in (a0 [all lanes], a1 [lanes 0..7])
    float m = hi ? fmaxf(a0, a1) : a0;
    #pragma unroll
    for (int off = 16; off; off >>= 1) m = fmaxf(m, __shfl_xor_sync(0xffffffffu, m, off));

    float s = __expf(a0 - m) + (hi ? __expf(a1 - m) : 0.f);
    #pragma unroll
    for (int off = 16; off; off >>= 1) s += __shfl_xor_sync(0xffffffffu, s, off);

    float lse = m + logf(s);
    float* o = out + (size_t)row * DOUT;
    o[lane] = a0 - lse;
    if (hi) o[32 + lane] = a1 - lse;
}

// ---------------------------------------------------------------------------
extern "C" void kernel_launch(void* const* d_in, const int* in_sizes, int n_in,
                              void* d_out, int out_size) {
    const float* x  = (const float*)d_in[0];
    const void*  ei = d_in[1];
    const float* ew = (const float*)d_in[2];
    const float* W1 = (const float*)d_in[3];
    const float* W2 = (const float*)d_in[4];
    float* out = (float*)d_out;

    static bool attr_set = false;
    const int g1_smem = (128 * 130 + DIN * DHID) * (int)sizeof(float);  // ~99.3 KB
    if (!attr_set) {
        cudaFuncSetAttribute(gemm1, cudaFuncAttributeMaxDynamicSharedMemorySize, g1_smem);
        attr_set = true;
    }

    detect_dtype<<<1, 256>>>((const long long*)ei);
    zero_deg<<<(NN + 1023) / 1024, 1024>>>();
    convert_hist<<<NE / 256, 256>>>(ei);
    scan_rows<<<1, 1024>>>();
    scatter<<<NE / 256, 256>>>(ew);
    gemm1<<<(NN + 127) / 128, 256, g1_smem>>>(x, W1);
    spmm1_csr<<<NN / 8, 256>>>();
    gemm2<<<(NN + 63) / 64, 256>>>(W2);
    spmm2_lsm<<<NN / 8, 256>>>(out);
}

// round 4
// speedup vs baseline: 1.5006x; 1.5006x over previous
#include <cuda_runtime.h>
#include <cuda_bf16.h>

#define NN 100000
#define NE 3200000
#define DIN 128
#define DHID 64
#define DOUT 40

#define SCAN_BLK 256
#define NSCAN ((NN + SCAN_BLK - 1) / SCAN_BLK)   // 391

// Scratch (static __device__ arrays — no allocation). 16B-aligned for vector ops.
__device__ __align__(16) float g_h1[NN * DHID];      // x@W1
__device__ __align__(16) float g_h1agg[NN * DHID];   // relu(spmm1)
__device__ __align__(16) float g_h2[NN * DOUT];      // h1agg@W2
__device__ int   g_dst[NE];
__device__ int   g_src[NE];
__device__ int2  g_edges[NE];      // CSR payload: (src, w-bits), sorted by dst
__device__ int   g_deg[NN];        // histogram
__device__ int   g_cur[NN];        // scatter cursors
__device__ int   g_rowptr[NN + 1];
__device__ int   g_rowloc[NN];     // within-block exclusive prefix
__device__ int   g_blocksum[NSCAN];
__device__ int   g_blockoff[NSCAN];
__device__ int   g_is_i32;

// ---------------------------------------------------------------------------
// packed fp32x2 FMA (Blackwell FFMA2 — only reachable via PTX)
// ---------------------------------------------------------------------------
union F2U { float2 f; unsigned long long u; };
__device__ __forceinline__ float2 ffma2(float2 a, float2 b, float2 c) {
    F2U ua, ub, uc, ud;
    ua.f = a; ub.f = b; uc.f = c;
    asm("fma.rn.f32x2 %0, %1, %2, %3;" : "=l"(ud.u) : "l"(ua.u), "l"(ub.u), "l"(uc.u));
    return ud.f;
}

// ---------------------------------------------------------------------------
// dtype detection (int32 vs int64 edge_index), deterministic
// ---------------------------------------------------------------------------
__global__ void detect_dtype(const long long* __restrict__ ei) {
    __shared__ int bad;
    if (threadIdx.x == 0) bad = 0;
    __syncthreads();
    long long v = ei[threadIdx.x];   // first 2KB, safe for either dtype
    if (v < 0 || v >= NN) atomicOr(&bad, 1);
    __syncthreads();
    if (threadIdx.x == 0) g_is_i32 = bad;
}

// ---------------------------------------------------------------------------
// zero degree histogram
// ---------------------------------------------------------------------------
__global__ void zero_deg() {
    int i = blockIdx.x * blockDim.x + threadIdx.x;
    if (i < NN) g_deg[i] = 0;
}

// ---------------------------------------------------------------------------
// convert edges (clamped) + degree histogram
// ---------------------------------------------------------------------------
__global__ void convert_hist(const void* __restrict__ eiv) {
    int i = blockIdx.x * blockDim.x + threadIdx.x;   // grid covers NE exactly
    int d, s;
    if (g_is_i32) {
        const int* e = (const int*)eiv;
        d = e[i]; s = e[NE + i];
    } else {
        const long long* e = (const long long*)eiv;
        d = (int)e[i]; s = (int)e[NE + i];
    }
    d = min(max(d, 0), NN - 1);
    s = min(max(s, 0), NN - 1);
    g_dst[i] = d;
    g_src[i] = s;
    atomicAdd(&g_deg[d], 1);
}

// ---------------------------------------------------------------------------
// 3-phase device-wide exclusive scan of g_deg -> g_rowptr, g_cur
// ---------------------------------------------------------------------------
__global__ void scan_phase1() {
    __shared__ int sm[SCAN_BLK];
    int t = threadIdx.x;
    int row = blockIdx.x * SCAN_BLK + t;
    int d = (row < NN) ? g_deg[row] : 0;
    sm[t] = d;
    __syncthreads();
    #pragma unroll
    for (int off = 1; off < SCAN_BLK; off <<= 1) {
        int v = (t >= off) ? sm[t - off] : 0;
        __syncthreads();
        sm[t] += v;
        __syncthreads();
    }
    if (row < NN) g_rowloc[row] = sm[t] - d;               // exclusive
    if (t == SCAN_BLK - 1) g_blocksum[blockIdx.x] = sm[t]; // block total
}

__global__ void scan_phase2() {   // one block, 512 threads (NSCAN=391 <= 512)
    __shared__ int sm[512];
    int t = threadIdx.x;
    int v = (t < NSCAN) ? g_blocksum[t] : 0;
    sm[t] = v;
    __syncthreads();
    #pragma unroll
    for (int off = 1; off < 512; off <<= 1) {
        int u = (t >= off) ? sm[t - off] : 0;
        __syncthreads();
        sm[t] += u;
        __syncthreads();
    }
    if (t < NSCAN) g_blockoff[t] = sm[t] - v;   // exclusive
}

__global__ void scan_phase3() {
    int row = blockIdx.x * 256 + threadIdx.x;
    if (row < NN) {
        int v = g_rowloc[row] + g_blockoff[row / SCAN_BLK];
        g_rowptr[row] = v;
        g_cur[row]    = v;
    } else if (row == NN) {
        g_rowptr[NN] = NE;
    }
}

// ---------------------------------------------------------------------------
// scatter edges into CSR order (packed (src, w) per edge)
// ---------------------------------------------------------------------------
__global__ void scatter(const float* __restrict__ ew) {
    int e = blockIdx.x * blockDim.x + threadIdx.x;   // grid covers NE exactly
    int d = g_dst[e];
    int pos = atomicAdd(&g_cur[d], 1);
    g_edges[pos] = make_int2(g_src[e], __float_as_int(ew[e]));
}

// ---------------------------------------------------------------------------
// GEMM1: h1 = x[NN,128] @ W1[128,64]
// Block tile 128x64, 256 threads, thread tile 8x4, f32x2 FMAs.
// ---------------------------------------------------------------------------
__global__ void gemm1(const float* __restrict__ x, const float* __restrict__ W1) {
    extern __shared__ float sm[];
    float (*Xs)[130] = (float(*)[130])sm;     // 128 x 130 (pad: conflict-free)
    float* Ws = sm + 128 * 130;               // [k][n] 128x64

    const int tid  = threadIdx.x;
    const int row0 = blockIdx.x * 128;

    {
        const float4* W4 = (const float4*)W1;
        float4*       Wd = (float4*)Ws;
        #pragma unroll
        for (int i = 0; i < 8; i++) Wd[tid + 256 * i] = W4[tid + 256 * i];
    }
    {
        const float4* X4 = (const float4*)x;
        #pragma unroll
        for (int i = 0; i < 16; i++) {
            int idx = tid + 256 * i;
            int r = idx >> 5, c4 = idx & 31;
            int gr = row0 + r;
            if (gr >= NN) gr = NN - 1;  // clamp (only last block)
            float4 v = X4[(size_t)gr * 32 + c4];
            Xs[r][c4 * 4 + 0] = v.x;
            Xs[r][c4 * 4 + 1] = v.y;
            Xs[r][c4 * 4 + 2] = v.z;
            Xs[r][c4 * 4 + 3] = v.w;
        }
    }
    __syncthreads();

    const int ty = tid >> 4;   // 0..15 -> rows ty*8..+7
    const int tx = tid & 15;   // 0..15 -> cols tx*4..+3

    float2 acc[8][2];
    #pragma unroll
    for (int r = 0; r < 8; r++) { acc[r][0] = make_float2(0.f, 0.f); acc[r][1] = make_float2(0.f, 0.f); }

    for (int k = 0; k < DIN; k++) {
        float4 w = *(const float4*)&Ws[k * DHID + tx * 4];
        float2 w01 = make_float2(w.x, w.y);
        float2 w23 = make_float2(w.z, w.w);
        #pragma unroll
        for (int r = 0; r < 8; r++) {
            float xv = Xs[ty * 8 + r][k];
            float2 xx = make_float2(xv, xv);
            acc[r][0] = ffma2(xx, w01, acc[r][0]);
            acc[r][1] = ffma2(xx, w23, acc[r][1]);
        }
    }

    float4* out = (float4*)g_h1;
    #pragma unroll
    for (int r = 0; r < 8; r++) {
        int gr = row0 + ty * 8 + r;
        if (gr < NN) {
            float4 v = make_float4(acc[r][0].x, acc[r][0].y, acc[r][1].x, acc[r][1].y);
            out[(size_t)gr * 16 + tx] = v;
        }
    }
}

// ---------------------------------------------------------------------------
// SpMM1 (CSR pull) + ReLU: h1agg[row] = relu(sum_e w_e * h1[src_e])
// One warp per row; lane holds cols {lane, lane+32}.
// ---------------------------------------------------------------------------
__global__ void spmm1_csr() {
    int row  = blockIdx.x * 8 + (threadIdx.x >> 5);
    int lane = threadIdx.x & 31;
    int beg = g_rowptr[row];
    int end = g_rowptr[row + 1];

    float a0 = 0.f, a1 = 0.f;
    int i = beg;
    for (; i + 4 <= end; i += 4) {
        int2 e0 = g_edges[i + 0];
        int2 e1 = g_edges[i + 1];
        int2 e2 = g_edges[i + 2];
        int2 e3 = g_edges[i + 3];
        const float* p0 = g_h1 + (size_t)e0.x * DHID;
        const float* p1 = g_h1 + (size_t)e1.x * DHID;
        const float* p2 = g_h1 + (size_t)e2.x * DHID;
        const float* p3 = g_h1 + (size_t)e3.x * DHID;
        float w0 = __int_as_float(e0.y), w1 = __int_as_float(e1.y);
        float w2 = __int_as_float(e2.y), w3 = __int_as_float(e3.y);
        float v00 = p0[lane], v01 = p0[32 + lane];
        float v10 = p1[lane], v11 = p1[32 + lane];
        float v20 = p2[lane], v21 = p2[32 + lane];
        float v30 = p3[lane], v31 = p3[32 + lane];
        a0 += w0 * v00; a1 += w0 * v01;
        a0 += w1 * v10; a1 += w1 * v11;
        a0 += w2 * v20; a1 += w2 * v21;
        a0 += w3 * v30; a1 += w3 * v31;
    }
    for (; i < end; i++) {
        int2 e = g_edges[i];
        const float* p = g_h1 + (size_t)e.x * DHID;
        float w = __int_as_float(e.y);
        a0 += w * p[lane];
        a1 += w * p[32 + lane];
    }
    g_h1agg[(size_t)row * DHID + lane]      = fmaxf(a0, 0.f);
    g_h1agg[(size_t)row * DHID + 32 + lane] = fmaxf(a1, 0.f);
}

// ---------------------------------------------------------------------------
// GEMM2: h2 = h1agg[NN,64] @ W2[64,40]   (input already ReLU'd)
// ---------------------------------------------------------------------------
__global__ void gemm2(const float* __restrict__ W2) {
    __shared__ float Hs[64][DHID + 1];
    __shared__ float Ws[DHID * DOUT];

    const int tid  = threadIdx.x;
    const int row0 = blockIdx.x * 64;

    #pragma unroll
    for (int i = 0; i < 16; i++) {
        int idx = tid + 256 * i;
        int r = idx >> 6, c = idx & 63;
        float v = 0.f;
        if (row0 + r < NN) v = g_h1agg[(size_t)(row0 + r) * DHID + c];
        Hs[r][c] = v;
    }
    #pragma unroll
    for (int i = 0; i < 10; i++) Ws[tid + 256 * i] = W2[tid + 256 * i];
    __syncthreads();

    const int ty = tid >> 3;  // 0..31 -> rows ty*2, ty*2+1
    const int tx = tid & 7;   // 0..7  -> cols tx*5..tx*5+4

    float acc[2][5] = {};
    #pragma unroll 8
    for (int k = 0; k < DHID; k++) {
        float h0  = Hs[ty * 2 + 0][k];
        float h1v = Hs[ty * 2 + 1][k];
        #pragma unroll
        for (int j = 0; j < 5; j++) {
            float w = Ws[k * DOUT + tx * 5 + j];
            acc[0][j] += h0 * w;
            acc[1][j] += h1v * w;
        }
    }

    #pragma unroll
    for (int i = 0; i < 2; i++) {
        int r = row0 + ty * 2 + i;
        if (r < NN) {
            #pragma unroll
            for (int j = 0; j < 5; j++)
                g_h2[(size_t)r * DOUT + tx * 5 + j] = acc[i][j];
        }
    }
}

// ---------------------------------------------------------------------------
// SpMM2 (CSR pull) + log_softmax fused. One warp per row.
// Lane holds col lane; lanes 0..7 also hold col 32+lane.
// ---------------------------------------------------------------------------
__global__ void spmm2_lsm(float* __restrict__ out) {
    int row  = blockIdx.x * 8 + (threadIdx.x >> 5);
    int lane = threadIdx.x & 31;
    bool hi  = lane < 8;
    int beg = g_rowptr[row];
    int end = g_rowptr[row + 1];

    float a0 = 0.f, a1 = 0.f;
    int i = beg;
    for (; i + 4 <= end; i += 4) {
        int2 e0 = g_edges[i + 0];
        int2 e1 = g_edges[i + 1];
        int2 e2 = g_edges[i + 2];
        int2 e3 = g_edges[i + 3];
        const float* p0 = g_h2 + (size_t)e0.x * DOUT;
        const float* p1 = g_h2 + (size_t)e1.x * DOUT;
        const float* p2 = g_h2 + (size_t)e2.x * DOUT;
        const float* p3 = g_h2 + (size_t)e3.x * DOUT;
        float w0 = __int_as_float(e0.y), w1 = __int_as_float(e1.y);
        float w2 = __int_as_float(e2.y), w3 = __int_as_float(e3.y);
        a0 += w0 * p0[lane];
        a0 += w1 * p1[lane];
        a0 += w2 * p2[lane];
        a0 += w3 * p3[lane];
        if (hi) {
            a1 += w0 * p0[32 + lane];
            a1 += w1 * p1[32 + lane];
            a1 += w2 * p2[32 + lane];
            a1 += w3 * p3[32 + lane];
        }
    }
    for (; i < end; i++) {
        int2 e = g_edges[i];
        const float* p = g_h2 + (size_t)e.x * DOUT;
        float w = __int_as_float(e.y);
        a0 += w * p[lane];
        if (hi) a1 += w * p[32 + lane];
    }

    // log_softmax over the 40 values held in (a0 [all lanes], a1 [lanes 0..7])
    float m = hi ? fmaxf(a0, a1) : a0;
    #pragma unroll
    for (int off = 16; off; off >>= 1) m = fmaxf(m, __shfl_xor_sync(0xffffffffu, m, off));

    float s = __expf(a0 - m) + (hi ? __expf(a1 - m) : 0.f);
    #pragma unroll
    for (int off = 16; off; off >>= 1) s += __shfl_xor_sync(0xffffffffu, s, off);

    float lse = m + logf(s);
    float* o = out + (size_t)row * DOUT;
    o[lane] = a0 - lse;
    if (hi) o[32 + lane] = a1 - lse;
}

// ---------------------------------------------------------------------------
extern "C" void kernel_launch(void* const* d_in, const int* in_sizes, int n_in,
                              void* d_out, int out_size) {
    const float* x  = (const float*)d_in[0];
    const void*  ei = d_in[1];
    const float* ew = (const float*)d_in[2];
    const float* W1 = (const float*)d_in[3];
    const float* W2 = (const float*)d_in[4];
    float* out = (float*)d_out;

    static bool attr_set = false;
    const int g1_smem = (128 * 130 + DIN * DHID) * (int)sizeof(float);  // ~99.3 KB
    if (!attr_set) {
        cudaFuncSetAttribute(gemm1, cudaFuncAttributeMaxDynamicSharedMemorySize, g1_smem);
        attr_set = true;
    }

    detect_dtype<<<1, 256>>>((const long long*)ei);
    zero_deg<<<(NN + 1023) / 1024, 1024>>>();
    convert_hist<<<NE / 256, 256>>>(ei);
    scan_phase1<<<NSCAN, SCAN_BLK>>>();
    scan_phase2<<<1, 512>>>();
    scan_phase3<<<(NN + 256) / 256, 256>>>();
    scatter<<<NE / 256, 256>>>(ew);
    gemm1<<<(NN + 127) / 128, 256, g1_smem>>>(x, W1);
    spmm1_csr<<<NN / 8, 256>>>();
    gemm2<<<(NN + 63) / 64, 256>>>(W2);
    spmm2_lsm<<<NN / 8, 256>>>(out);
}